// round 1
// baseline (speedup 1.0000x reference)
#include <cuda_runtime.h>
#include <math.h>

// Problem constants
#define BN 4
#define VN 4096
#define KN 128
#define CN 128
#define CI 16
#define NBLK 4
#define NCHUNK 32   // split-K chunks for x_spec (V=4096 / 128)

typedef unsigned long long ull;

// ---------------- scratch (device globals; no allocation allowed) ----------------
__device__ float g_x    [BN*VN*CN];
__device__ float g_GXe  [BN*VN*KN];
__device__ float g_GYe  [BN*VN*KN];
__device__ float g_xdiff[BN*VN*CN];
__device__ float g_gx   [BN*VN*CN];
__device__ float g_gy   [BN*VN*CN];
__device__ float g_gfeat[BN*VN*CN];
__device__ float g_br   [BN*VN*CN];
__device__ float g_bi   [BN*VN*CN];
__device__ float g_h0   [BN*VN*CN];
__device__ float g_h1   [BN*VN*CN];
__device__ float g_part [NCHUNK*BN*KN*CN];
__device__ float g_s    [BN*KN*CN];

// ---------------- f32x2 packed-FMA helpers (sm_103a) ----------------
__device__ __forceinline__ ull pack2(float lo, float hi) {
    ull r; asm("mov.b64 %0, {%1, %2};" : "=l"(r) : "f"(lo), "f"(hi)); return r;
}
__device__ __forceinline__ float2 unpack2(ull v) {
    float2 f; asm("mov.b64 {%0, %1}, %2;" : "=f"(f.x), "=f"(f.y) : "l"(v)); return f;
}
__device__ __forceinline__ void ffma2(ull &d, ull a, ull b) {
    asm("fma.rn.f32x2 %0, %1, %2, %0;" : "+l"(d) : "l"(a), "l"(b));
}

// ---------------- 128x128 tile SGEMM core, BK=16, 256 threads, 8x8/thread ----------
// As, Bs: k-major [16][128] smem tiles. Thread (tx=tid&15, ty=tid>>4) owns
// rows {ty*4..+3, 64+ty*4..+3}, cols {tx*4..+3, 64+tx*4..+3}.
__device__ __forceinline__ void acc_zero(ull acc[8][4]) {
#pragma unroll
    for (int i = 0; i < 8; i++)
#pragma unroll
        for (int p = 0; p < 4; p++) acc[i][p] = 0ULL;
}
__device__ __forceinline__ int row_of(int i, int ty) { return i < 4 ? ty*4+i : 64+ty*4+(i-4); }
__device__ __forceinline__ int col_of(int p, int tx) { return p < 2 ? tx*4+2*p : 64+tx*4+2*(p-2); }

__device__ __forceinline__ void mm_step16(const float* __restrict__ As,
                                          const float* __restrict__ Bs,
                                          ull acc[8][4], int tx, int ty)
{
#pragma unroll
    for (int kk = 0; kk < 16; kk++) {
        const float* ar = As + kk*128;
        const float* br = Bs + kk*128;
        float4 a0 = *(const float4*)(ar + ty*4);
        float4 a1 = *(const float4*)(ar + 64 + ty*4);
        float4 b0 = *(const float4*)(br + tx*4);
        float4 b1 = *(const float4*)(br + 64 + tx*4);
        ull bp[4] = { pack2(b0.x,b0.y), pack2(b0.z,b0.w),
                      pack2(b1.x,b1.y), pack2(b1.z,b1.w) };
        float av[8] = {a0.x,a0.y,a0.z,a0.w,a1.x,a1.y,a1.z,a1.w};
#pragma unroll
        for (int i = 0; i < 8; i++) {
            ull ap = pack2(av[i], av[i]);
#pragma unroll
            for (int p = 0; p < 4; p++) ffma2(acc[i][p], ap, bp[p]);
        }
    }
}

// Load A tile [128 rows x 16 k] (row-major, stride lda) transposed into As[k][m].
__device__ __forceinline__ void load_At(float* As, const float* __restrict__ A, int lda, int tid)
{
#pragma unroll
    for (int r = 0; r < 2; r++) {
        int f   = tid + r*256;
        int row = f >> 2;
        int k4  = (f & 3) * 4;
        float4 v = *(const float4*)(A + (size_t)row*lda + k4);
        As[(k4+0)*128 + row] = v.x;
        As[(k4+1)*128 + row] = v.y;
        As[(k4+2)*128 + row] = v.z;
        As[(k4+3)*128 + row] = v.w;
    }
}
// Load B tile [16 k x 128 n] (row-major, stride ldb) directly into Bs[k][n].
__device__ __forceinline__ void load_B(float* Bs, const float* __restrict__ Bsrc, int ldb, int tid)
{
#pragma unroll
    for (int r = 0; r < 2; r++) {
        int f  = tid + r*256;
        int k  = f >> 5;
        int n4 = (f & 31) * 4;
        *(float4*)(Bs + k*128 + n4) = *(const float4*)(Bsrc + (size_t)k*ldb + n4);
    }
}
__device__ __forceinline__ void load_B_neg(float* Bs, const float* __restrict__ Bsrc, int ldb, int tid)
{
#pragma unroll
    for (int r = 0; r < 2; r++) {
        int f  = tid + r*256;
        int k  = f >> 5;
        int n4 = (f & 31) * 4;
        float4 v = *(const float4*)(Bsrc + (size_t)k*ldb + n4);
        v.x = -v.x; v.y = -v.y; v.z = -v.z; v.w = -v.w;
        *(float4*)(Bs + k*128 + n4) = v;
    }
}
__device__ __forceinline__ void load_B_rowscale(float* Bs, const float* __restrict__ Bsrc,
                                                int ldb, const float* __restrict__ rs, int tid)
{
#pragma unroll
    for (int r = 0; r < 2; r++) {
        int f  = tid + r*256;
        int k  = f >> 5;
        int n4 = (f & 31) * 4;
        float s  = rs[k];
        float4 v = *(const float4*)(Bsrc + (size_t)k*ldb + n4);
        v.x *= s; v.y *= s; v.z *= s; v.w *= s;
        *(float4*)(Bs + k*128 + n4) = v;
    }
}

// Standard NN GEMM accumulation: acc += A[128, 16*ktiles] @ B[16*ktiles, 128]
__device__ __forceinline__ void gemm_acc(ull acc[8][4],
                                         const float* __restrict__ A, int lda,
                                         const float* __restrict__ Bm, int ldb,
                                         int ktiles, bool negB,
                                         float* As, float* Bs, int tid, int tx, int ty)
{
    for (int kt = 0; kt < ktiles; kt++) {
        load_At(As, A + kt*16, lda, tid);
        if (negB) load_B_neg(Bs, Bm + (size_t)kt*16*ldb, ldb, tid);
        else      load_B    (Bs, Bm + (size_t)kt*16*ldb, ldb, tid);
        __syncthreads();
        mm_step16(As, Bs, acc, tx, ty);
        __syncthreads();
    }
}

// ---------------- kernels ----------------

// x = x_in @ Wf + bf     (M = B*V tiles of 128, K = 16)
__global__ void __launch_bounds__(256) k_lin_in(const float* __restrict__ x_in,
                                                const float* __restrict__ Wf,
                                                const float* __restrict__ bf)
{
    __shared__ __align__(16) float As[16*128], Bs[16*128];
    int tid = threadIdx.x, tx = tid & 15, ty = tid >> 4;
    int mt = blockIdx.x;
    ull acc[8][4]; acc_zero(acc);
    gemm_acc(acc, x_in + (size_t)mt*128*CI, CI, Wf, CN, 1, false, As, Bs, tid, tx, ty);
    float* Cp = g_x + (size_t)mt*128*CN;
#pragma unroll
    for (int i = 0; i < 8; i++) { int r = row_of(i, ty);
#pragma unroll
        for (int p = 0; p < 4; p++) { int c0 = col_of(p, tx);
            float2 v = unpack2(acc[i][p]);
            v.x += bf[c0]; v.y += bf[c0+1];
            *(float2*)(Cp + (size_t)r*CN + c0) = v;
        }
    }
}

// GXe = gradX @ evecs, GYe = gradY @ evecs  (per batch, K = 4096). THE heavy kernel.
__global__ void __launch_bounds__(256) k_grad_pre(const float* __restrict__ gX,
                                                  const float* __restrict__ gY,
                                                  const float* __restrict__ evecs)
{
    __shared__ __align__(16) float As[16*128], Bs[16*128];
    int tid = threadIdx.x, tx = tid & 15, ty = tid >> 4;
    int mt = blockIdx.x, b = blockIdx.y, z = blockIdx.z;
    const float* A  = (z ? gY : gX) + (size_t)b*VN*VN + (size_t)mt*128*VN;
    const float* Bm = evecs + (size_t)b*VN*KN;
    float* Cp = (z ? g_GYe : g_GXe) + (size_t)b*VN*KN + (size_t)mt*128*KN;
    ull acc[8][4]; acc_zero(acc);
    gemm_acc(acc, A, VN, Bm, KN, VN/16, false, As, Bs, tid, tx, ty);
#pragma unroll
    for (int i = 0; i < 8; i++) { int r = row_of(i, ty);
#pragma unroll
        for (int p = 0; p < 4; p++) { int c0 = col_of(p, tx);
            float2 v = unpack2(acc[i][p]);
            *(float2*)(Cp + (size_t)r*KN + c0) = v;
        }
    }
}

// partial x_spec: part[ch,b,k,c] = sum_{v in chunk ch} evecs[b,v,k] * x[b,v,c] * mass[b,v]
__global__ void __launch_bounds__(256) k_spec_part(const float* __restrict__ evecs,
                                                   const float* __restrict__ mass)
{
    __shared__ __align__(16) float As[16*128], Bs[16*128];
    int tid = threadIdx.x, tx = tid & 15, ty = tid >> 4;
    int ch = blockIdx.x, b = blockIdx.y;
    const float* Ev = evecs + (size_t)b*VN*KN + (size_t)ch*128*KN;
    const float* Xp = g_x   + (size_t)b*VN*CN + (size_t)ch*128*CN;
    const float* mp = mass  + (size_t)b*VN    + (size_t)ch*128;
    ull acc[8][4]; acc_zero(acc);
    for (int v0 = 0; v0 < 128; v0 += 16) {
        load_B(As, Ev + (size_t)v0*KN, KN, tid);               // As[v][k] (reduction = v)
        load_B_rowscale(Bs, Xp + (size_t)v0*CN, CN, mp + v0, tid); // Bs[v][c] = x*mass
        __syncthreads();
        mm_step16(As, Bs, acc, tx, ty);
        __syncthreads();
    }
    float* Cp = g_part + ((size_t)ch*BN + b)*KN*CN;
#pragma unroll
    for (int i = 0; i < 8; i++) { int r = row_of(i, ty);
#pragma unroll
        for (int p = 0; p < 4; p++) { int c0 = col_of(p, tx);
            float2 v = unpack2(acc[i][p]);
            *(float2*)(Cp + (size_t)r*CN + c0) = v;
        }
    }
}

// s[b,k,c] = exp(-evals[b,k]*max(t[i,c],1e-8)) * sum_ch part[ch,b,k,c]
__global__ void k_spec_reduce(const float* __restrict__ evals,
                              const float* __restrict__ t, int iblk)
{
    int b = blockIdx.y;
    int idx = blockIdx.x*256 + threadIdx.x;      // < K*C
    float sum = 0.f;
#pragma unroll 8
    for (int ch = 0; ch < NCHUNK; ch++)
        sum += g_part[((size_t)ch*BN + b)*KN*CN + idx];
    int k = idx >> 7, c = idx & 127;
    float ti = fmaxf(t[iblk*CN + c], 1e-8f);
    g_s[(size_t)b*KN*CN + idx] = expf(-evals[b*KN + k]*ti) * sum;
}

// z=0: x_diff = evecs@s   z=1: gx = GXe@s   z=2: gy = GYe@s   (K = 128)
__global__ void __launch_bounds__(256) k_fb3(const float* __restrict__ evecs)
{
    __shared__ __align__(16) float As[16*128], Bs[16*128];
    int tid = threadIdx.x, tx = tid & 15, ty = tid >> 4;
    int mt = blockIdx.x, b = blockIdx.y, z = blockIdx.z;
    size_t aoff = (size_t)b*VN*KN + (size_t)mt*128*KN;
    const float* A  = (z == 0 ? evecs + aoff : (z == 1 ? g_GXe + aoff : g_GYe + aoff));
    const float* Bm = g_s + (size_t)b*KN*CN;
    float* Cp = (z == 0 ? g_xdiff : z == 1 ? g_gx : g_gy)
                + (size_t)b*VN*CN + (size_t)mt*128*CN;
    ull acc[8][4]; acc_zero(acc);
    gemm_acc(acc, A, KN, Bm, CN, 8, false, As, Bs, tid, tx, ty);
#pragma unroll
    for (int i = 0; i < 8; i++) { int r = row_of(i, ty);
#pragma unroll
        for (int p = 0; p < 4; p++) { int c0 = col_of(p, tx);
            float2 v = unpack2(acc[i][p]);
            *(float2*)(Cp + (size_t)r*CN + c0) = v;
        }
    }
}

// z=0: br = gx@Are - gy@Aim   z=1: bi = gy@Are + gx@Aim
__global__ void __launch_bounds__(256) k_complex(const float* __restrict__ Are,
                                                 const float* __restrict__ Aim, int iblk)
{
    __shared__ __align__(16) float As[16*128], Bs[16*128];
    int tid = threadIdx.x, tx = tid & 15, ty = tid >> 4;
    int mt = blockIdx.x, b = blockIdx.y, z = blockIdx.z;
    size_t toff = (size_t)b*VN*CN + (size_t)mt*128*CN;
    const float* A1 = (z ? g_gy : g_gx) + toff;
    const float* A2 = (z ? g_gx : g_gy) + toff;
    const float* B1 = Are + (size_t)iblk*KN*CN;
    const float* B2 = Aim + (size_t)iblk*KN*CN;
    ull acc[8][4]; acc_zero(acc);
    gemm_acc(acc, A1, CN, B1, CN, 8, false,     As, Bs, tid, tx, ty);
    gemm_acc(acc, A2, CN, B2, CN, 8, (z == 0),  As, Bs, tid, tx, ty);
    float* Cp = (z ? g_bi : g_br) + toff;
#pragma unroll
    for (int i = 0; i < 8; i++) { int r = row_of(i, ty);
#pragma unroll
        for (int p = 0; p < 4; p++) { int c0 = col_of(p, tx);
            float2 v = unpack2(acc[i][p]);
            *(float2*)(Cp + (size_t)r*CN + c0) = v;
        }
    }
}

// gfeat = tanh(gx*br + gy*bi)
__global__ void k_tanh()
{
    size_t idx = (size_t)blockIdx.x*256 + threadIdx.x;
    g_gfeat[idx] = tanhf(fmaf(g_gx[idx], g_br[idx], g_gy[idx]*g_bi[idx]));
}

// h0 = relu([x | x_diff | gfeat] @ W0[i] + b0[i])   (K = 384 in 3 segments)
__global__ void __launch_bounds__(256) k_mlp0(const float* __restrict__ W0,
                                              const float* __restrict__ b0, int iblk)
{
    __shared__ __align__(16) float As[16*128], Bs[16*128];
    int tid = threadIdx.x, tx = tid & 15, ty = tid >> 4;
    int mt = blockIdx.x, b = blockIdx.y;
    size_t toff = (size_t)b*VN*CN + (size_t)mt*128*CN;
    const float* segs[3] = { g_x + toff, g_xdiff + toff, g_gfeat + toff };
    const float* W = W0 + (size_t)iblk*3*CN*CN;
    ull acc[8][4]; acc_zero(acc);
#pragma unroll
    for (int seg = 0; seg < 3; seg++)
        gemm_acc(acc, segs[seg], CN, W + (size_t)seg*CN*CN, CN, 8, false, As, Bs, tid, tx, ty);
    const float* bb = b0 + iblk*CN;
    float* Cp = g_h0 + toff;
#pragma unroll
    for (int i = 0; i < 8; i++) { int r = row_of(i, ty);
#pragma unroll
        for (int p = 0; p < 4; p++) { int c0 = col_of(p, tx);
            float2 v = unpack2(acc[i][p]);
            v.x = fmaxf(v.x + bb[c0],   0.f);
            v.y = fmaxf(v.y + bb[c0+1], 0.f);
            *(float2*)(Cp + (size_t)r*CN + c0) = v;
        }
    }
}

// h1 = relu(h0 @ W1[i] + b1[i])
__global__ void __launch_bounds__(256) k_mlp1(const float* __restrict__ W1,
                                              const float* __restrict__ b1, int iblk)
{
    __shared__ __align__(16) float As[16*128], Bs[16*128];
    int tid = threadIdx.x, tx = tid & 15, ty = tid >> 4;
    int mt = blockIdx.x, b = blockIdx.y;
    size_t toff = (size_t)b*VN*CN + (size_t)mt*128*CN;
    ull acc[8][4]; acc_zero(acc);
    gemm_acc(acc, g_h0 + toff, CN, W1 + (size_t)iblk*CN*CN, CN, 8, false, As, Bs, tid, tx, ty);
    const float* bb = b1 + iblk*CN;
    float* Cp = g_h1 + toff;
#pragma unroll
    for (int i = 0; i < 8; i++) { int r = row_of(i, ty);
#pragma unroll
        for (int p = 0; p < 4; p++) { int c0 = col_of(p, tx);
            float2 v = unpack2(acc[i][p]);
            v.x = fmaxf(v.x + bb[c0],   0.f);
            v.y = fmaxf(v.y + bb[c0+1], 0.f);
            *(float2*)(Cp + (size_t)r*CN + c0) = v;
        }
    }
}

// x += h1 @ W2[i] + b2[i]
__global__ void __launch_bounds__(256) k_mlp2(const float* __restrict__ W2,
                                              const float* __restrict__ b2, int iblk)
{
    __shared__ __align__(16) float As[16*128], Bs[16*128];
    int tid = threadIdx.x, tx = tid & 15, ty = tid >> 4;
    int mt = blockIdx.x, b = blockIdx.y;
    size_t toff = (size_t)b*VN*CN + (size_t)mt*128*CN;
    ull acc[8][4]; acc_zero(acc);
    gemm_acc(acc, g_h1 + toff, CN, W2 + (size_t)iblk*CN*CN, CN, 8, false, As, Bs, tid, tx, ty);
    const float* bb = b2 + iblk*CN;
    float* Cp = g_x + toff;
#pragma unroll
    for (int i = 0; i < 8; i++) { int r = row_of(i, ty);
#pragma unroll
        for (int p = 0; p < 4; p++) { int c0 = col_of(p, tx);
            float2 v = unpack2(acc[i][p]);
            float2 xv = *(const float2*)(Cp + (size_t)r*CN + c0);
            v.x += xv.x + bb[c0];
            v.y += xv.y + bb[c0+1];
            *(float2*)(Cp + (size_t)r*CN + c0) = v;
        }
    }
}

// out = x @ Wl + bl
__global__ void __launch_bounds__(256) k_out(const float* __restrict__ Wl,
                                             const float* __restrict__ bl,
                                             float* __restrict__ out)
{
    __shared__ __align__(16) float As[16*128], Bs[16*128];
    int tid = threadIdx.x, tx = tid & 15, ty = tid >> 4;
    int mt = blockIdx.x, b = blockIdx.y;
    size_t toff = (size_t)b*VN*CN + (size_t)mt*128*CN;
    ull acc[8][4]; acc_zero(acc);
    gemm_acc(acc, g_x + toff, CN, Wl, CN, 8, false, As, Bs, tid, tx, ty);
    float* Cp = out + toff;
#pragma unroll
    for (int i = 0; i < 8; i++) { int r = row_of(i, ty);
#pragma unroll
        for (int p = 0; p < 4; p++) { int c0 = col_of(p, tx);
            float2 v = unpack2(acc[i][p]);
            v.x += bl[c0]; v.y += bl[c0+1];
            *(float2*)(Cp + (size_t)r*CN + c0) = v;
        }
    }
}

// ---------------- launcher ----------------
extern "C" void kernel_launch(void* const* d_in, const int* in_sizes, int n_in,
                              void* d_out, int out_size)
{
    if (n_in < 19) return;
    const float* x_in  = (const float*)d_in[0];
    const float* mass  = (const float*)d_in[1];
    const float* evals = (const float*)d_in[2];
    const float* evecs = (const float*)d_in[3];
    const float* gradX = (const float*)d_in[4];
    const float* gradY = (const float*)d_in[5];
    const float* Wf    = (const float*)d_in[6];
    const float* bf    = (const float*)d_in[7];
    const float* Wl    = (const float*)d_in[8];
    const float* bl    = (const float*)d_in[9];
    const float* t     = (const float*)d_in[10];
    const float* Are   = (const float*)d_in[11];
    const float* Aim   = (const float*)d_in[12];
    const float* W0    = (const float*)d_in[13];
    const float* b0    = (const float*)d_in[14];
    const float* W1    = (const float*)d_in[15];
    const float* b1    = (const float*)d_in[16];
    const float* W2    = (const float*)d_in[17];
    const float* b2    = (const float*)d_in[18];

    // x = x_in @ Wf + bf
    k_lin_in<<<BN*VN/128, 256>>>(x_in, Wf, bf);
    // One-time heavy precompute: GXe = gradX@evecs, GYe = gradY@evecs
    k_grad_pre<<<dim3(VN/128, BN, 2), 256>>>(gradX, gradY, evecs);

    for (int i = 0; i < NBLK; i++) {
        k_spec_part  <<<dim3(NCHUNK, BN), 256>>>(evecs, mass);
        k_spec_reduce<<<dim3(KN*CN/256, BN), 256>>>(evals, t, i);
        k_fb3        <<<dim3(VN/128, BN, 3), 256>>>(evecs);
        k_complex    <<<dim3(VN/128, BN, 2), 256>>>(Are, Aim, i);
        k_tanh       <<<BN*VN*CN/256, 256>>>();
        k_mlp0       <<<dim3(VN/128, BN), 256>>>(W0, b0, i);
        k_mlp1       <<<dim3(VN/128, BN), 256>>>(W1, b1, i);
        k_mlp2       <<<dim3(VN/128, BN), 256>>>(W2, b2, i);
    }
    // out = x @ Wl + bl
    k_out<<<dim3(VN/128, BN), 256>>>(Wl, bl, (float*)d_out);
}

// round 6
// speedup vs baseline: 1.2706x; 1.2706x over previous
#include <cuda_runtime.h>
#include <cuda_fp16.h>
#include <math.h>
#include <stdint.h>

// Problem constants
#define BN 4
#define VN 4096
#define KN 128
#define CN 128
#define CI 16
#define NBLK 4
#define NCHUNK 32

typedef unsigned long long ull;

// ---------------- scratch (device globals; no allocation allowed) ----------------
__device__ __align__(256) float g_x    [BN*VN*CN];
__device__ __align__(256) float g_GXe  [BN*VN*KN];
__device__ __align__(256) float g_GYe  [BN*VN*KN];
__device__ __align__(256) float g_xdiff[BN*VN*CN];
__device__ __align__(256) float g_gx   [BN*VN*CN];
__device__ __align__(256) float g_gy   [BN*VN*CN];
__device__ __align__(256) float g_gfeat[BN*VN*CN];
__device__ __align__(256) float g_br   [BN*VN*CN];
__device__ __align__(256) float g_bi   [BN*VN*CN];
__device__ __align__(256) float g_h0   [BN*VN*CN];
__device__ __align__(256) float g_h1   [BN*VN*CN];
__device__ __align__(256) float g_part [NCHUNK*BN*KN*CN];
__device__ __align__(256) float g_s    [BN*KN*CN];
// evecs transposed + fp16 hi/lo split (x64): [b][k(eigen)][v]
__device__ __align__(256) __half g_evT_h[BN*KN*VN];
__device__ __align__(256) __half g_evT_l[BN*KN*VN];

// ---------------- f32x2 packed-FMA helpers (sm_103a) ----------------
__device__ __forceinline__ ull pack2(float lo, float hi) {
    ull r; asm("mov.b64 %0, {%1, %2};" : "=l"(r) : "f"(lo), "f"(hi)); return r;
}
__device__ __forceinline__ float2 unpack2(ull v) {
    float2 f; asm("mov.b64 {%0, %1}, %2;" : "=f"(f.x), "=f"(f.y) : "l"(v)); return f;
}
__device__ __forceinline__ void ffma2(ull &d, ull a, ull b) {
    asm("fma.rn.f32x2 %0, %1, %2, %0;" : "+l"(d) : "l"(a), "l"(b));
}

// ---------------- warp MMA (m16n8k16 f16->f32) ----------------
__device__ __forceinline__ void mma16816(float* c, const unsigned* a, const unsigned* b) {
    asm volatile("mma.sync.aligned.m16n8k16.row.col.f32.f16.f16.f32 "
        "{%0,%1,%2,%3}, {%4,%5,%6,%7}, {%8,%9}, {%0,%1,%2,%3};"
        : "+f"(c[0]), "+f"(c[1]), "+f"(c[2]), "+f"(c[3])
        : "r"(a[0]), "r"(a[1]), "r"(a[2]), "r"(a[3]), "r"(b[0]), "r"(b[1]));
}

// 128x128 block tile, 8 warps as 2(M)x4(N), warp tile 64x32.
// As: [128][LD] row=m col=k.  Bs: [128][LD] row=n col=k.
template<int LD>
__device__ __forceinline__ void mma_pass(const __half* As, const __half* Bs,
                                         float acc[4][4][4], int wm, int wn,
                                         int lane, int ksteps)
{
    const int ra = wm*64 + (lane>>2);
    const int rb = wn*32 + (lane>>2);
    const int kc = 2*(lane&3);
    for (int ks = 0; ks < ksteps; ks++) {
        const int k0 = ks*16 + kc;
        unsigned a[4][4], bf[4][2];
#pragma unroll
        for (int mi = 0; mi < 4; mi++) {
            const __half* p = As + (ra + mi*16)*LD + k0;
            a[mi][0] = *(const unsigned*)p;
            a[mi][1] = *(const unsigned*)(p + 8*LD);
            a[mi][2] = *(const unsigned*)(p + 8);
            a[mi][3] = *(const unsigned*)(p + 8*LD + 8);
        }
#pragma unroll
        for (int ni = 0; ni < 4; ni++) {
            const __half* p = Bs + (rb + ni*8)*LD + k0;
            bf[ni][0] = *(const unsigned*)p;
            bf[ni][1] = *(const unsigned*)(p + 8);
        }
#pragma unroll
        for (int mi = 0; mi < 4; mi++)
#pragma unroll
            for (int ni = 0; ni < 4; ni++)
                mma16816(acc[mi][ni], a[mi], bf[ni]);
    }
}

// ---------------- evecs transpose + fp16 split (x64): [b][v][k] -> [b][k][v] --------
__global__ void k_evT(const float* __restrict__ evecs) {
    __shared__ float tile[32][33];
    int b = blockIdx.z;
    int k0 = blockIdx.x * 32, v0 = blockIdx.y * 32;
    int tx = threadIdx.x, ty = threadIdx.y;
    const float* src = evecs + (size_t)b * VN * KN;
#pragma unroll
    for (int j = 0; j < 32; j += 8)
        tile[ty + j][tx] = src[(size_t)(v0 + ty + j) * KN + k0 + tx] * 64.f;
    __syncthreads();
#pragma unroll
    for (int j = 0; j < 32; j += 8) {
        int k = k0 + ty + j, v = v0 + tx;
        float x = tile[tx][ty + j];
        __half h = __float2half_rn(x);
        size_t o = ((size_t)b * KN + k) * VN + v;
        g_evT_h[o] = h;
        g_evT_l[o] = __float2half_rn(x - __half2float(h));
    }
}

// ---------------- MMA grad precompute: GXe = gradX@evecs (fp32 out) ----------------
// M=128 rows, N=128 eigen, K=4096 in 64 chunks of 64. fp16 hi/lo 3-term split.
#define LDC 72
#define SEG (128*LDC)
#define SMEM_GP (4*SEG*2)   // Ah, Al, Bh, Bl -> 73728 bytes

__global__ void __launch_bounds__(256, 2) k_grad_pre_mma(const float* __restrict__ gX,
                                                         const float* __restrict__ gY)
{
    extern __shared__ __half sm[];
    __half* Ah = sm;
    __half* Al = sm + SEG;
    __half* Bh_s = sm + 2*SEG;
    __half* Bl_s = sm + 3*SEG;

    int tid = threadIdx.x, lane = tid & 31, wid = tid >> 5;
    int wm = wid >> 2, wn = wid & 3;
    int mt = blockIdx.x, b = blockIdx.y, z = blockIdx.z;

    const float* A = (z ? gY : gX) + (size_t)b*VN*VN + (size_t)mt*128*VN;
    const __half* Bh = g_evT_h + (size_t)b*KN*VN;
    const __half* Bl = g_evT_l + (size_t)b*KN*VN;

    float acc[4][4][4];
#pragma unroll
    for (int i = 0; i < 4; i++)
#pragma unroll
        for (int j = 0; j < 4; j++)
#pragma unroll
            for (int q = 0; q < 4; q++) acc[i][j][q] = 0.f;

    for (int c = 0; c < 64; c++) {
        int v0 = c * 64;
        // A tile: 128 rows x 64 cols fp32 -> scaled x64 hi/lo halves
#pragma unroll
        for (int r = 0; r < 8; r++) {
            int idx = tid + r*256;
            int row = idx >> 4, c4 = idx & 15;
            float4 v = *(const float4*)(A + (size_t)row*VN + v0 + c4*4);
            float x0 = v.x*64.f, x1 = v.y*64.f, x2 = v.z*64.f, x3 = v.w*64.f;
            __half h0 = __float2half_rn(x0), h1 = __float2half_rn(x1);
            __half h2 = __float2half_rn(x2), h3 = __float2half_rn(x3);
            __half2* ph = (__half2*)(Ah + row*LDC + c4*4);
            ph[0] = __halves2half2(h0, h1);
            ph[1] = __halves2half2(h2, h3);
            __half l0 = __float2half_rn(x0 - __half2float(h0));
            __half l1 = __float2half_rn(x1 - __half2float(h1));
            __half l2 = __float2half_rn(x2 - __half2float(h2));
            __half l3 = __float2half_rn(x3 - __half2float(h3));
            __half2* pl = (__half2*)(Al + row*LDC + c4*4);
            pl[0] = __halves2half2(l0, l1);
            pl[1] = __halves2half2(l2, l3);
        }
        // B tile: evT 128 rows(eigen k) x 64 cols(v) fp16 h/l
#pragma unroll
        for (int r = 0; r < 4; r++) {
            int idx = tid + r*256;
            int row = idx >> 3, q = idx & 7;
            *(uint4*)(Bh_s + row*LDC + q*8) = *(const uint4*)(Bh + (size_t)row*VN + v0 + q*8);
            *(uint4*)(Bl_s + row*LDC + q*8) = *(const uint4*)(Bl + (size_t)row*VN + v0 + q*8);
        }
        __syncthreads();
        mma_pass<LDC>(Ah, Bh_s, acc, wm, wn, lane, 4);
        mma_pass<LDC>(Ah, Bl_s, acc, wm, wn, lane, 4);
        mma_pass<LDC>(Al, Bh_s, acc, wm, wn, lane, 4);
        __syncthreads();
    }

    // acc = 4096 * GXe_true -> store fp32 GXe
    float* Cp = (z ? g_GYe : g_GXe) + ((size_t)b*VN + mt*128)*KN;
    const float sc = 1.f/4096.f;
#pragma unroll
    for (int mi = 0; mi < 4; mi++) {
#pragma unroll
        for (int ni = 0; ni < 4; ni++) {
            int r0 = wm*64 + mi*16 + (lane>>2);
            int cc = wn*32 + ni*8 + 2*(lane&3);
            *(float2*)(Cp + (size_t)r0*KN + cc) =
                make_float2(acc[mi][ni][0]*sc, acc[mi][ni][1]*sc);
            *(float2*)(Cp + (size_t)(r0+8)*KN + cc) =
                make_float2(acc[mi][ni][2]*sc, acc[mi][ni][3]*sc);
        }
    }
}

// ---------------- SIMT 128x128 tile SGEMM core (verified R1 machinery) -------------
__device__ __forceinline__ void acc_zero(ull acc[8][4]) {
#pragma unroll
    for (int i = 0; i < 8; i++)
#pragma unroll
        for (int p = 0; p < 4; p++) acc[i][p] = 0ULL;
}
__device__ __forceinline__ int row_of(int i, int ty) { return i < 4 ? ty*4+i : 64+ty*4+(i-4); }
__device__ __forceinline__ int col_of(int p, int tx) { return p < 2 ? tx*4+2*p : 64+tx*4+2*(p-2); }

__device__ __forceinline__ void mm_step16(const float* __restrict__ As,
                                          const float* __restrict__ Bs,
                                          ull acc[8][4], int tx, int ty)
{
#pragma unroll
    for (int kk = 0; kk < 16; kk++) {
        const float* ar = As + kk*128;
        const float* br = Bs + kk*128;
        float4 a0 = *(const float4*)(ar + ty*4);
        float4 a1 = *(const float4*)(ar + 64 + ty*4);
        float4 b0 = *(const float4*)(br + tx*4);
        float4 b1 = *(const float4*)(br + 64 + tx*4);
        ull bp[4] = { pack2(b0.x,b0.y), pack2(b0.z,b0.w),
                      pack2(b1.x,b1.y), pack2(b1.z,b1.w) };
        float av[8] = {a0.x,a0.y,a0.z,a0.w,a1.x,a1.y,a1.z,a1.w};
#pragma unroll
        for (int i = 0; i < 8; i++) {
            ull ap = pack2(av[i], av[i]);
#pragma unroll
            for (int p = 0; p < 4; p++) ffma2(acc[i][p], ap, bp[p]);
        }
    }
}
__device__ __forceinline__ void load_At(float* As, const float* __restrict__ A, int lda, int tid)
{
#pragma unroll
    for (int r = 0; r < 2; r++) {
        int f   = tid + r*256;
        int row = f >> 2;
        int k4  = (f & 3) * 4;
        float4 v = *(const float4*)(A + (size_t)row*lda + k4);
        As[(k4+0)*128 + row] = v.x;
        As[(k4+1)*128 + row] = v.y;
        As[(k4+2)*128 + row] = v.z;
        As[(k4+3)*128 + row] = v.w;
    }
}
__device__ __forceinline__ void load_B(float* Bs, const float* __restrict__ Bsrc, int ldb, int tid)
{
#pragma unroll
    for (int r = 0; r < 2; r++) {
        int f  = tid + r*256;
        int k  = f >> 5;
        int n4 = (f & 31) * 4;
        *(float4*)(Bs + k*128 + n4) = *(const float4*)(Bsrc + (size_t)k*ldb + n4);
    }
}
__device__ __forceinline__ void load_B_neg(float* Bs, const float* __restrict__ Bsrc, int ldb, int tid)
{
#pragma unroll
    for (int r = 0; r < 2; r++) {
        int f  = tid + r*256;
        int k  = f >> 5;
        int n4 = (f & 31) * 4;
        float4 v = *(const float4*)(Bsrc + (size_t)k*ldb + n4);
        v.x = -v.x; v.y = -v.y; v.z = -v.z; v.w = -v.w;
        *(float4*)(Bs + k*128 + n4) = v;
    }
}
__device__ __forceinline__ void load_B_rowscale(float* Bs, const float* __restrict__ Bsrc,
                                                int ldb, const float* __restrict__ rs, int tid)
{
#pragma unroll
    for (int r = 0; r < 2; r++) {
        int f  = tid + r*256;
        int k  = f >> 5;
        int n4 = (f & 31) * 4;
        float s  = rs[k];
        float4 v = *(const float4*)(Bsrc + (size_t)k*ldb + n4);
        v.x *= s; v.y *= s; v.z *= s; v.w *= s;
        *(float4*)(Bs + k*128 + n4) = v;
    }
}
__device__ __forceinline__ void gemm_acc(ull acc[8][4],
                                         const float* __restrict__ A, int lda,
                                         const float* __restrict__ Bm, int ldb,
                                         int ktiles, bool negB,
                                         float* As, float* Bs, int tid, int tx, int ty)
{
    for (int kt = 0; kt < ktiles; kt++) {
        load_At(As, A + kt*16, lda, tid);
        if (negB) load_B_neg(Bs, Bm + (size_t)kt*16*ldb, ldb, tid);
        else      load_B    (Bs, Bm + (size_t)kt*16*ldb, ldb, tid);
        __syncthreads();
        mm_step16(As, Bs, acc, tx, ty);
        __syncthreads();
    }
}

// ---------------- SIMT kernels (verbatim from the PASSING R1 build) ----------------
__global__ void __launch_bounds__(256) k_lin_in(const float* __restrict__ x_in,
                                                const float* __restrict__ Wf,
                                                const float* __restrict__ bf)
{
    __shared__ __align__(16) float As[16*128], Bs[16*128];
    int tid = threadIdx.x, tx = tid & 15, ty = tid >> 4;
    int mt = blockIdx.x;
    ull acc[8][4]; acc_zero(acc);
    gemm_acc(acc, x_in + (size_t)mt*128*CI, CI, Wf, CN, 1, false, As, Bs, tid, tx, ty);
    float* Cp = g_x + (size_t)mt*128*CN;
#pragma unroll
    for (int i = 0; i < 8; i++) { int r = row_of(i, ty);
#pragma unroll
        for (int p = 0; p < 4; p++) { int c0 = col_of(p, tx);
            float2 v = unpack2(acc[i][p]);
            v.x += bf[c0]; v.y += bf[c0+1];
            *(float2*)(Cp + (size_t)r*CN + c0) = v;
        }
    }
}

__global__ void __launch_bounds__(256) k_spec_part(const float* __restrict__ evecs,
                                                   const float* __restrict__ mass)
{
    __shared__ __align__(16) float As[16*128], Bs[16*128];
    int tid = threadIdx.x, tx = tid & 15, ty = tid >> 4;
    int ch = blockIdx.x, b = blockIdx.y;
    const float* Ev = evecs + (size_t)b*VN*KN + (size_t)ch*128*KN;
    const float* Xp = g_x   + (size_t)b*VN*CN + (size_t)ch*128*CN;
    const float* mp = mass  + (size_t)b*VN    + (size_t)ch*128;
    ull acc[8][4]; acc_zero(acc);
    for (int v0 = 0; v0 < 128; v0 += 16) {
        load_B(As, Ev + (size_t)v0*KN, KN, tid);
        load_B_rowscale(Bs, Xp + (size_t)v0*CN, CN, mp + v0, tid);
        __syncthreads();
        mm_step16(As, Bs, acc, tx, ty);
        __syncthreads();
    }
    float* Cp = g_part + ((size_t)ch*BN + b)*KN*CN;
#pragma unroll
    for (int i = 0; i < 8; i++) { int r = row_of(i, ty);
#pragma unroll
        for (int p = 0; p < 4; p++) { int c0 = col_of(p, tx);
            float2 v = unpack2(acc[i][p]);
            *(float2*)(Cp + (size_t)r*CN + c0) = v;
        }
    }
}

__global__ void k_spec_reduce(const float* __restrict__ evals,
                              const float* __restrict__ t, int iblk)
{
    int b = blockIdx.y;
    int idx = blockIdx.x*256 + threadIdx.x;
    float sum = 0.f;
#pragma unroll 8
    for (int ch = 0; ch < NCHUNK; ch++)
        sum += g_part[((size_t)ch*BN + b)*KN*CN + idx];
    int k = idx >> 7, c = idx & 127;
    float ti = fmaxf(t[iblk*CN + c], 1e-8f);
    g_s[(size_t)b*KN*CN + idx] = expf(-evals[b*KN + k]*ti) * sum;
}

__global__ void __launch_bounds__(256) k_fb3(const float* __restrict__ evecs)
{
    __shared__ __align__(16) float As[16*128], Bs[16*128];
    int tid = threadIdx.x, tx = tid & 15, ty = tid >> 4;
    int mt = blockIdx.x, b = blockIdx.y, z = blockIdx.z;
    size_t aoff = (size_t)b*VN*KN + (size_t)mt*128*KN;
    const float* A  = (z == 0 ? evecs + aoff : (z == 1 ? g_GXe + aoff : g_GYe + aoff));
    const float* Bm = g_s + (size_t)b*KN*CN;
    float* Cp = (z == 0 ? g_xdiff : z == 1 ? g_gx : g_gy)
                + (size_t)b*VN*CN + (size_t)mt*128*CN;
    ull acc[8][4]; acc_zero(acc);
    gemm_acc(acc, A, KN, Bm, CN, 8, false, As, Bs, tid, tx, ty);
#pragma unroll
    for (int i = 0; i < 8; i++) { int r = row_of(i, ty);
#pragma unroll
        for (int p = 0; p < 4; p++) { int c0 = col_of(p, tx);
            float2 v = unpack2(acc[i][p]);
            *(float2*)(Cp + (size_t)r*CN + c0) = v;
        }
    }
}

__global__ void __launch_bounds__(256) k_complex(const float* __restrict__ Are,
                                                 const float* __restrict__ Aim, int iblk)
{
    __shared__ __align__(16) float As[16*128], Bs[16*128];
    int tid = threadIdx.x, tx = tid & 15, ty = tid >> 4;
    int mt = blockIdx.x, b = blockIdx.y, z = blockIdx.z;
    size_t toff = (size_t)b*VN*CN + (size_t)mt*128*CN;
    const float* A1 = (z ? g_gy : g_gx) + toff;
    const float* A2 = (z ? g_gx : g_gy) + toff;
    const float* B1 = Are + (size_t)iblk*KN*CN;
    const float* B2 = Aim + (size_t)iblk*KN*CN;
    ull acc[8][4]; acc_zero(acc);
    gemm_acc(acc, A1, CN, B1, CN, 8, false,     As, Bs, tid, tx, ty);
    gemm_acc(acc, A2, CN, B2, CN, 8, (z == 0),  As, Bs, tid, tx, ty);
    float* Cp = (z ? g_bi : g_br) + toff;
#pragma unroll
    for (int i = 0; i < 8; i++) { int r = row_of(i, ty);
#pragma unroll
        for (int p = 0; p < 4; p++) { int c0 = col_of(p, tx);
            float2 v = unpack2(acc[i][p]);
            *(float2*)(Cp + (size_t)r*CN + c0) = v;
        }
    }
}

__global__ void k_tanh()
{
    size_t idx = (size_t)blockIdx.x*256 + threadIdx.x;
    g_gfeat[idx] = tanhf(fmaf(g_gx[idx], g_br[idx], g_gy[idx]*g_bi[idx]));
}

__global__ void __launch_bounds__(256) k_mlp0(const float* __restrict__ W0,
                                              const float* __restrict__ b0, int iblk)
{
    __shared__ __align__(16) float As[16*128], Bs[16*128];
    int tid = threadIdx.x, tx = tid & 15, ty = tid >> 4;
    int mt = blockIdx.x, b = blockIdx.y;
    size_t toff = (size_t)b*VN*CN + (size_t)mt*128*CN;
    const float* segs[3] = { g_x + toff, g_xdiff + toff, g_gfeat + toff };
    const float* W = W0 + (size_t)iblk*3*CN*CN;
    ull acc[8][4]; acc_zero(acc);
#pragma unroll
    for (int seg = 0; seg < 3; seg++)
        gemm_acc(acc, segs[seg], CN, W + (size_t)seg*CN*CN, CN, 8, false, As, Bs, tid, tx, ty);
    const float* bb = b0 + iblk*CN;
    float* Cp = g_h0 + toff;
#pragma unroll
    for (int i = 0; i < 8; i++) { int r = row_of(i, ty);
#pragma unroll
        for (int p = 0; p < 4; p++) { int c0 = col_of(p, tx);
            float2 v = unpack2(acc[i][p]);
            v.x = fmaxf(v.x + bb[c0],   0.f);
            v.y = fmaxf(v.y + bb[c0+1], 0.f);
            *(float2*)(Cp + (size_t)r*CN + c0) = v;
        }
    }
}

__global__ void __launch_bounds__(256) k_mlp1(const float* __restrict__ W1,
                                              const float* __restrict__ b1, int iblk)
{
    __shared__ __align__(16) float As[16*128], Bs[16*128];
    int tid = threadIdx.x, tx = tid & 15, ty = tid >> 4;
    int mt = blockIdx.x, b = blockIdx.y;
    size_t toff = (size_t)b*VN*CN + (size_t)mt*128*CN;
    ull acc[8][4]; acc_zero(acc);
    gemm_acc(acc, g_h0 + toff, CN, W1 + (size_t)iblk*CN*CN, CN, 8, false, As, Bs, tid, tx, ty);
    const float* bb = b1 + iblk*CN;
    float* Cp = g_h1 + toff;
#pragma unroll
    for (int i = 0; i < 8; i++) { int r = row_of(i, ty);
#pragma unroll
        for (int p = 0; p < 4; p++) { int c0 = col_of(p, tx);
            float2 v = unpack2(acc[i][p]);
            v.x = fmaxf(v.x + bb[c0],   0.f);
            v.y = fmaxf(v.y + bb[c0+1], 0.f);
            *(float2*)(Cp + (size_t)r*CN + c0) = v;
        }
    }
}

__global__ void __launch_bounds__(256) k_mlp2(const float* __restrict__ W2,
                                              const float* __restrict__ b2, int iblk)
{
    __shared__ __align__(16) float As[16*128], Bs[16*128];
    int tid = threadIdx.x, tx = tid & 15, ty = tid >> 4;
    int mt = blockIdx.x, b = blockIdx.y;
    size_t toff = (size_t)b*VN*CN + (size_t)mt*128*CN;
    ull acc[8][4]; acc_zero(acc);
    gemm_acc(acc, g_h1 + toff, CN, W2 + (size_t)iblk*CN*CN, CN, 8, false, As, Bs, tid, tx, ty);
    const float* bb = b2 + iblk*CN;
    float* Cp = g_x + toff;
#pragma unroll
    for (int i = 0; i < 8; i++) { int r = row_of(i, ty);
#pragma unroll
        for (int p = 0; p < 4; p++) { int c0 = col_of(p, tx);
            float2 v = unpack2(acc[i][p]);
            float2 xv = *(const float2*)(Cp + (size_t)r*CN + c0);
            v.x += xv.x + bb[c0];
            v.y += xv.y + bb[c0+1];
            *(float2*)(Cp + (size_t)r*CN + c0) = v;
        }
    }
}

__global__ void __launch_bounds__(256) k_out(const float* __restrict__ Wl,
                                             const float* __restrict__ bl,
                                             float* __restrict__ out)
{
    __shared__ __align__(16) float As[16*128], Bs[16*128];
    int tid = threadIdx.x, tx = tid & 15, ty = tid >> 4;
    int mt = blockIdx.x, b = blockIdx.y;
    size_t toff = (size_t)b*VN*CN + (size_t)mt*128*CN;
    ull acc[8][4]; acc_zero(acc);
    gemm_acc(acc, g_x + toff, CN, Wl, CN, 8, false, As, Bs, tid, tx, ty);
    float* Cp = out + toff;
#pragma unroll
    for (int i = 0; i < 8; i++) { int r = row_of(i, ty);
#pragma unroll
        for (int p = 0; p < 4; p++) { int c0 = col_of(p, tx);
            float2 v = unpack2(acc[i][p]);
            v.x += bl[c0]; v.y += bl[c0+1];
            *(float2*)(Cp + (size_t)r*CN + c0) = v;
        }
    }
}

// ---------------- launcher ----------------
extern "C" void kernel_launch(void* const* d_in, const int* in_sizes, int n_in,
                              void* d_out, int out_size)
{
    if (n_in < 19) return;
    const float* x_in  = (const float*)d_in[0];
    const float* mass  = (const float*)d_in[1];
    const float* evals = (const float*)d_in[2];
    const float* evecs = (const float*)d_in[3];
    const float* gradX = (const float*)d_in[4];
    const float* gradY = (const float*)d_in[5];
    const float* Wf    = (const float*)d_in[6];
    const float* bf    = (const float*)d_in[7];
    const float* Wl    = (const float*)d_in[8];
    const float* bl    = (const float*)d_in[9];
    const float* t     = (const float*)d_in[10];
    const float* Are   = (const float*)d_in[11];
    const float* Aim   = (const float*)d_in[12];
    const float* W0    = (const float*)d_in[13];
    const float* b0    = (const float*)d_in[14];
    const float* W1    = (const float*)d_in[15];
    const float* b1    = (const float*)d_in[16];
    const float* W2    = (const float*)d_in[17];
    const float* b2    = (const float*)d_in[18];

    cudaFuncSetAttribute(k_grad_pre_mma, cudaFuncAttributeMaxDynamicSharedMemorySize,
                         SMEM_GP);

    // one-time preps
    k_evT<<<dim3(KN/32, VN/32, BN), dim3(32, 8)>>>(evecs);
    k_lin_in<<<BN*VN/128, 256>>>(x_in, Wf, bf);
    // heavy precompute on tensor cores (fp16 hi/lo split, fp32 out)
    k_grad_pre_mma<<<dim3(VN/128, BN, 2), 256, SMEM_GP>>>(gradX, gradY);

    for (int i = 0; i < NBLK; i++) {
        k_spec_part  <<<dim3(NCHUNK, BN), 256>>>(evecs, mass);
        k_spec_reduce<<<dim3(KN*CN/256, BN), 256>>>(evals, t, i);
        k_fb3        <<<dim3(VN/128, BN, 3), 256>>>(evecs);
        k_complex    <<<dim3(VN/128, BN, 2), 256>>>(Are, Aim, i);
        k_tanh       <<<BN*VN*CN/256, 256>>>();
        k_mlp0       <<<dim3(VN/128, BN), 256>>>(W0, b0, i);
        k_mlp1       <<<dim3(VN/128, BN), 256>>>(W1, b1, i);
        k_mlp2       <<<dim3(VN/128, BN), 256>>>(W2, b2, i);
    }
    k_out<<<dim3(VN/128, BN), 256>>>(Wl, bl, (float*)d_out);
}

// round 12
// speedup vs baseline: 1.3415x; 1.0557x over previous
#include <cuda_runtime.h>
#include <cuda_fp16.h>
#include <math.h>
#include <stdint.h>

// Problem constants
#define BN 4
#define VN 4096
#define KN 128
#define CN 128
#define CI 16
#define NBLK 4
#define NCHUNK 32

typedef unsigned long long ull;

// ---------------- scratch (device globals; no allocation allowed) ----------------
__device__ __align__(256) float g_x    [BN*VN*CN];
__device__ __align__(256) float g_GXe  [BN*VN*KN];
__device__ __align__(256) float g_GYe  [BN*VN*KN];
__device__ __align__(256) float g_xdiff[BN*VN*CN];
__device__ __align__(256) float g_gx   [BN*VN*CN];
__device__ __align__(256) float g_gy   [BN*VN*CN];
__device__ __align__(256) float g_gfeat[BN*VN*CN];
__device__ __align__(256) float g_br   [BN*VN*CN];
__device__ __align__(256) float g_bi   [BN*VN*CN];
__device__ __align__(256) float g_h0   [BN*VN*CN];
__device__ __align__(256) float g_h1   [BN*VN*CN];
__device__ __align__(256) float g_part [NCHUNK*BN*KN*CN];
// s transposed + fp16 hi/lo split (x8): [b][c][k]
__device__ __align__(256) __half g_sT_h[BN*CN*KN];
__device__ __align__(256) __half g_sT_l[BN*CN*KN];
// evecs transposed + fp16 hi/lo split (x64): [b][k(eigen)][v]
__device__ __align__(256) __half g_evT_h[BN*KN*VN];
__device__ __align__(256) __half g_evT_l[BN*KN*VN];

// ---------------- f32x2 packed-FMA helpers (sm_103a) ----------------
__device__ __forceinline__ ull pack2(float lo, float hi) {
    ull r; asm("mov.b64 %0, {%1, %2};" : "=l"(r) : "f"(lo), "f"(hi)); return r;
}
__device__ __forceinline__ float2 unpack2(ull v) {
    float2 f; asm("mov.b64 {%0, %1}, %2;" : "=f"(f.x), "=f"(f.y) : "l"(v)); return f;
}
__device__ __forceinline__ void ffma2(ull &d, ull a, ull b) {
    asm("fma.rn.f32x2 %0, %1, %2, %0;" : "+l"(d) : "l"(a), "l"(b));
}

// ---------------- warp MMA (m16n8k16 f16->f32) — VALIDATED in R6 ----------------
__device__ __forceinline__ void mma16816(float* c, const unsigned* a, const unsigned* b) {
    asm volatile("mma.sync.aligned.m16n8k16.row.col.f32.f16.f16.f32 "
        "{%0,%1,%2,%3}, {%4,%5,%6,%7}, {%8,%9}, {%0,%1,%2,%3};"
        : "+f"(c[0]), "+f"(c[1]), "+f"(c[2]), "+f"(c[3])
        : "r"(a[0]), "r"(a[1]), "r"(a[2]), "r"(a[3]), "r"(b[0]), "r"(b[1]));
}

// 128x128 block tile, 8 warps as 2(M)x4(N), warp tile 64x32.
template<int LD>
__device__ __forceinline__ void mma_pass(const __half* As, const __half* Bs,
                                         float acc[4][4][4], int wm, int wn,
                                         int lane, int ksteps)
{
    const int ra = wm*64 + (lane>>2);
    const int rb = wn*32 + (lane>>2);
    const int kc = 2*(lane&3);
    for (int ks = 0; ks < ksteps; ks++) {
        const int k0 = ks*16 + kc;
        unsigned a[4][4], bf[4][2];
#pragma unroll
        for (int mi = 0; mi < 4; mi++) {
            const __half* p = As + (ra + mi*16)*LD + k0;
            a[mi][0] = *(const unsigned*)p;
            a[mi][1] = *(const unsigned*)(p + 8*LD);
            a[mi][2] = *(const unsigned*)(p + 8);
            a[mi][3] = *(const unsigned*)(p + 8*LD + 8);
        }
#pragma unroll
        for (int ni = 0; ni < 4; ni++) {
            const __half* p = Bs + (rb + ni*8)*LD + k0;
            bf[ni][0] = *(const unsigned*)p;
            bf[ni][1] = *(const unsigned*)(p + 8);
        }
#pragma unroll
        for (int mi = 0; mi < 4; mi++)
#pragma unroll
            for (int ni = 0; ni < 4; ni++)
                mma16816(acc[mi][ni], a[mi], bf[ni]);
    }
}

__device__ __forceinline__ void acc_clear(float acc[4][4][4]) {
#pragma unroll
    for (int i = 0; i < 4; i++)
#pragma unroll
        for (int j = 0; j < 4; j++)
#pragma unroll
            for (int q = 0; q < 4; q++) acc[i][j][q] = 0.f;
}

#define LDC 72
#define SEG (128*LDC)
#define SMEM_MMA (4*SEG*2)   // 73728 bytes (grad_pre only, pre-loop, validated)

// stage fp32 tile [128 rows][64 cols] (row stride lda, scaled) -> h/l smem [128][LDC]
// VALIDATED as the A-side staging of the passing grad_pre kernel.
__device__ __forceinline__ void stage_f32(__half* dh, __half* dl,
                                          const float* __restrict__ A, int lda,
                                          float s, int tid)
{
#pragma unroll
    for (int r = 0; r < 8; r++) {
        int idx = tid + r*256;
        int row = idx >> 4, c4 = idx & 15;
        float4 v = *(const float4*)(A + (size_t)row*lda + c4*4);
        float x0 = v.x*s, x1 = v.y*s, x2 = v.z*s, x3 = v.w*s;
        __half h0 = __float2half_rn(x0), h1 = __float2half_rn(x1);
        __half h2 = __float2half_rn(x2), h3 = __float2half_rn(x3);
        __half2* ph = (__half2*)(dh + row*LDC + c4*4);
        ph[0] = __halves2half2(h0, h1);
        ph[1] = __halves2half2(h2, h3);
        __half l0 = __float2half_rn(x0 - __half2float(h0));
        __half l1 = __float2half_rn(x1 - __half2float(h1));
        __half l2 = __float2half_rn(x2 - __half2float(h2));
        __half l3 = __float2half_rn(x3 - __half2float(h3));
        __half2* pl = (__half2*)(dl + row*LDC + c4*4);
        pl[0] = __halves2half2(l0, l1);
        pl[1] = __halves2half2(l2, l3);
    }
}

// ---------------- one-time prep kernels ----------------

// evecs [b][v][k] -> transposed fp16 split (x64): [b][k][v]   (VALIDATED)
__global__ void k_evT(const float* __restrict__ evecs) {
    __shared__ float tile[32][33];
    int b = blockIdx.z;
    int k0 = blockIdx.x * 32, v0 = blockIdx.y * 32;
    int tx = threadIdx.x, ty = threadIdx.y;
    const float* src = evecs + (size_t)b * VN * KN;
#pragma unroll
    for (int j = 0; j < 32; j += 8)
        tile[ty + j][tx] = src[(size_t)(v0 + ty + j) * KN + k0 + tx] * 64.f;
    __syncthreads();
#pragma unroll
    for (int j = 0; j < 32; j += 8) {
        int k = k0 + ty + j, v = v0 + tx;
        float x = tile[tx][ty + j];
        __half h = __float2half_rn(x);
        size_t o = ((size_t)b * KN + k) * VN + v;
        g_evT_h[o] = h;
        g_evT_l[o] = __float2half_rn(x - __half2float(h));
    }
}

// ---------------- MMA grad precompute (UNCHANGED from passing R6) ----------------
__global__ void __launch_bounds__(256, 2) k_grad_pre_mma(const float* __restrict__ gX,
                                                         const float* __restrict__ gY)
{
    extern __shared__ __half sm[];
    __half* Ah = sm;
    __half* Al = sm + SEG;
    __half* Bh_s = sm + 2*SEG;
    __half* Bl_s = sm + 3*SEG;

    int tid = threadIdx.x, lane = tid & 31, wid = tid >> 5;
    int wm = wid >> 2, wn = wid & 3;
    int mt = blockIdx.x, b = blockIdx.y, z = blockIdx.z;

    const float* A = (z ? gY : gX) + (size_t)b*VN*VN + (size_t)mt*128*VN;
    const __half* Bh = g_evT_h + (size_t)b*KN*VN;
    const __half* Bl = g_evT_l + (size_t)b*KN*VN;

    float acc[4][4][4]; acc_clear(acc);

    for (int c = 0; c < 64; c++) {
        int v0 = c * 64;
        stage_f32(Ah, Al, A + v0, VN, 64.f, tid);
#pragma unroll
        for (int r = 0; r < 4; r++) {
            int idx = tid + r*256;
            int row = idx >> 3, q = idx & 7;
            *(uint4*)(Bh_s + row*LDC + q*8) = *(const uint4*)(Bh + (size_t)row*VN + v0 + q*8);
            *(uint4*)(Bl_s + row*LDC + q*8) = *(const uint4*)(Bl + (size_t)row*VN + v0 + q*8);
        }
        __syncthreads();
        mma_pass<LDC>(Ah, Bh_s, acc, wm, wn, lane, 4);
        mma_pass<LDC>(Ah, Bl_s, acc, wm, wn, lane, 4);
        mma_pass<LDC>(Al, Bh_s, acc, wm, wn, lane, 4);
        __syncthreads();
    }

    float* Cp = (z ? g_GYe : g_GXe) + ((size_t)b*VN + mt*128)*KN;
    const float sc = 1.f/4096.f;
#pragma unroll
    for (int mi = 0; mi < 4; mi++) {
#pragma unroll
        for (int ni = 0; ni < 4; ni++) {
            int r0 = wm*64 + mi*16 + (lane>>2);
            int cc = wn*32 + ni*8 + 2*(lane&3);
            *(float2*)(Cp + (size_t)r0*KN + cc) =
                make_float2(acc[mi][ni][0]*sc, acc[mi][ni][1]*sc);
            *(float2*)(Cp + (size_t)(r0+8)*KN + cc) =
                make_float2(acc[mi][ni][2]*sc, acc[mi][ni][3]*sc);
        }
    }
}

// ---------------- fb3 via MMA — STATIC smem (40KB), CK=32 chunks --------------------
// z0: xdiff = evecs@s  z1: gx = GXe@s  z2: gy = GYe@s
// A: fp32 staged x64.  B: pre-split fp16 sT_h/l [c][k] (x8), raw-copied.
#define LD2 40
#define SEG2 (128*LD2)

__global__ void __launch_bounds__(256) k_fb3_mma(const float* __restrict__ evecs)
{
    __shared__ __align__(16) __half Ah[SEG2], Al[SEG2], Bh_s[SEG2], Bl_s[SEG2];

    int tid = threadIdx.x, lane = tid & 31, wid = tid >> 5;
    int wm = wid >> 2, wn = wid & 3;
    int mt = blockIdx.x, b = blockIdx.y, z = blockIdx.z;

    size_t aoff = ((size_t)b*VN + mt*128)*KN;
    const float* A = (z == 0 ? evecs + aoff : (z == 1 ? g_GXe + aoff : g_GYe + aoff));
    const __half* Bh = g_sT_h + (size_t)b*CN*KN;
    const __half* Bl = g_sT_l + (size_t)b*CN*KN;

    float acc[4][4][4]; acc_clear(acc);

    for (int c = 0; c < 4; c++) {
        int v0 = c * 32;
        // A tile: 128 rows x 32 cols fp32 -> x64 hi/lo halves
#pragma unroll
        for (int r = 0; r < 4; r++) {
            int idx = tid + r*256;
            int row = idx >> 3, c4 = idx & 7;
            float4 v = *(const float4*)(A + (size_t)row*KN + v0 + c4*4);
            float x0 = v.x*64.f, x1 = v.y*64.f, x2 = v.z*64.f, x3 = v.w*64.f;
            __half h0 = __float2half_rn(x0), h1 = __float2half_rn(x1);
            __half h2 = __float2half_rn(x2), h3 = __float2half_rn(x3);
            __half2* ph = (__half2*)(Ah + row*LD2 + c4*4);
            ph[0] = __halves2half2(h0, h1);
            ph[1] = __halves2half2(h2, h3);
            __half l0 = __float2half_rn(x0 - __half2float(h0));
            __half l1 = __float2half_rn(x1 - __half2float(h1));
            __half l2 = __float2half_rn(x2 - __half2float(h2));
            __half l3 = __float2half_rn(x3 - __half2float(h3));
            __half2* pl = (__half2*)(Al + row*LD2 + c4*4);
            pl[0] = __halves2half2(l0, l1);
            pl[1] = __halves2half2(l2, l3);
        }
        // B tile: 128 rows(c) x 32 halves, raw copy of pre-split sT
#pragma unroll
        for (int r = 0; r < 2; r++) {
            int idx = tid + r*256;
            int row = idx >> 2, q = idx & 3;
            *(uint4*)(Bh_s + row*LD2 + q*8) = *(const uint4*)(Bh + (size_t)row*KN + v0 + q*8);
            *(uint4*)(Bl_s + row*LD2 + q*8) = *(const uint4*)(Bl + (size_t)row*KN + v0 + q*8);
        }
        __syncthreads();
        mma_pass<LD2>(Ah, Bh_s, acc, wm, wn, lane, 2);
        mma_pass<LD2>(Ah, Bl_s, acc, wm, wn, lane, 2);
        mma_pass<LD2>(Al, Bh_s, acc, wm, wn, lane, 2);
        __syncthreads();
    }

    float* Cp = (z == 0 ? g_xdiff : z == 1 ? g_gx : g_gy) + ((size_t)b*VN + mt*128)*CN;
    const float sc = 1.f/512.f;   // A x64, B x8
#pragma unroll
    for (int mi = 0; mi < 4; mi++) {
#pragma unroll
        for (int ni = 0; ni < 4; ni++) {
            int r0 = wm*64 + mi*16 + (lane>>2);
            int cc = wn*32 + ni*8 + 2*(lane&3);
            *(float2*)(Cp + (size_t)r0*CN + cc) =
                make_float2(acc[mi][ni][0]*sc, acc[mi][ni][1]*sc);
            *(float2*)(Cp + (size_t)(r0+8)*CN + cc) =
                make_float2(acc[mi][ni][2]*sc, acc[mi][ni][3]*sc);
        }
    }
}

// ---------------- SIMT core (verified machinery, unchanged) ----------------
__device__ __forceinline__ void acc_zero(ull acc[8][4]) {
#pragma unroll
    for (int i = 0; i < 8; i++)
#pragma unroll
        for (int p = 0; p < 4; p++) acc[i][p] = 0ULL;
}
__device__ __forceinline__ int row_of(int i, int ty) { return i < 4 ? ty*4+i : 64+ty*4+(i-4); }
__device__ __forceinline__ int col_of(int p, int tx) { return p < 2 ? tx*4+2*p : 64+tx*4+2*(p-2); }

__device__ __forceinline__ void mm_step16(const float* __restrict__ As,
                                          const float* __restrict__ Bs,
                                          ull acc[8][4], int tx, int ty)
{
#pragma unroll
    for (int kk = 0; kk < 16; kk++) {
        const float* ar = As + kk*128;
        const float* br = Bs + kk*128;
        float4 a0 = *(const float4*)(ar + ty*4);
        float4 a1 = *(const float4*)(ar + 64 + ty*4);
        float4 b0 = *(const float4*)(br + tx*4);
        float4 b1 = *(const float4*)(br + 64 + tx*4);
        ull bp[4] = { pack2(b0.x,b0.y), pack2(b0.z,b0.w),
                      pack2(b1.x,b1.y), pack2(b1.z,b1.w) };
        float av[8] = {a0.x,a0.y,a0.z,a0.w,a1.x,a1.y,a1.z,a1.w};
#pragma unroll
        for (int i = 0; i < 8; i++) {
            ull ap = pack2(av[i], av[i]);
#pragma unroll
            for (int p = 0; p < 4; p++) ffma2(acc[i][p], ap, bp[p]);
        }
    }
}
__device__ __forceinline__ void load_At(float* As, const float* __restrict__ A, int lda, int tid)
{
#pragma unroll
    for (int r = 0; r < 2; r++) {
        int f   = tid + r*256;
        int row = f >> 2;
        int k4  = (f & 3) * 4;
        float4 v = *(const float4*)(A + (size_t)row*lda + k4);
        As[(k4+0)*128 + row] = v.x;
        As[(k4+1)*128 + row] = v.y;
        As[(k4+2)*128 + row] = v.z;
        As[(k4+3)*128 + row] = v.w;
    }
}
__device__ __forceinline__ void load_B(float* Bs, const float* __restrict__ Bsrc, int ldb, int tid)
{
#pragma unroll
    for (int r = 0; r < 2; r++) {
        int f  = tid + r*256;
        int k  = f >> 5;
        int n4 = (f & 31) * 4;
        *(float4*)(Bs + k*128 + n4) = *(const float4*)(Bsrc + (size_t)k*ldb + n4);
    }
}
__device__ __forceinline__ void load_B_neg(float* Bs, const float* __restrict__ Bsrc, int ldb, int tid)
{
#pragma unroll
    for (int r = 0; r < 2; r++) {
        int f  = tid + r*256;
        int k  = f >> 5;
        int n4 = (f & 31) * 4;
        float4 v = *(const float4*)(Bsrc + (size_t)k*ldb + n4);
        v.x = -v.x; v.y = -v.y; v.z = -v.z; v.w = -v.w;
        *(float4*)(Bs + k*128 + n4) = v;
    }
}
__device__ __forceinline__ void load_B_rowscale(float* Bs, const float* __restrict__ Bsrc,
                                                int ldb, const float* __restrict__ rs, int tid)
{
#pragma unroll
    for (int r = 0; r < 2; r++) {
        int f  = tid + r*256;
        int k  = f >> 5;
        int n4 = (f & 31) * 4;
        float s  = rs[k];
        float4 v = *(const float4*)(Bsrc + (size_t)k*ldb + n4);
        v.x *= s; v.y *= s; v.z *= s; v.w *= s;
        *(float4*)(Bs + k*128 + n4) = v;
    }
}
__device__ __forceinline__ void gemm_acc(ull acc[8][4],
                                         const float* __restrict__ A, int lda,
                                         const float* __restrict__ Bm, int ldb,
                                         int ktiles, bool negB,
                                         float* As, float* Bs, int tid, int tx, int ty)
{
    for (int kt = 0; kt < ktiles; kt++) {
        load_At(As, A + kt*16, lda, tid);
        if (negB) load_B_neg(Bs, Bm + (size_t)kt*16*ldb, ldb, tid);
        else      load_B    (Bs, Bm + (size_t)kt*16*ldb, ldb, tid);
        __syncthreads();
        mm_step16(As, Bs, acc, tx, ty);
        __syncthreads();
    }
}

__global__ void __launch_bounds__(256) k_lin_in(const float* __restrict__ x_in,
                                                const float* __restrict__ Wf,
                                                const float* __restrict__ bf)
{
    __shared__ __align__(16) float As[16*128], Bs[16*128];
    int tid = threadIdx.x, tx = tid & 15, ty = tid >> 4;
    int mt = blockIdx.x;
    ull acc[8][4]; acc_zero(acc);
    gemm_acc(acc, x_in + (size_t)mt*128*CI, CI, Wf, CN, 1, false, As, Bs, tid, tx, ty);
    float* Cp = g_x + (size_t)mt*128*CN;
#pragma unroll
    for (int i = 0; i < 8; i++) { int r = row_of(i, ty);
#pragma unroll
        for (int p = 0; p < 4; p++) { int c0 = col_of(p, tx);
            float2 v = unpack2(acc[i][p]);
            v.x += bf[c0]; v.y += bf[c0+1];
            *(float2*)(Cp + (size_t)r*CN + c0) = v;
        }
    }
}

__global__ void __launch_bounds__(256) k_spec_part(const float* __restrict__ evecs,
                                                   const float* __restrict__ mass)
{
    __shared__ __align__(16) float As[16*128], Bs[16*128];
    int tid = threadIdx.x, tx = tid & 15, ty = tid >> 4;
    int ch = blockIdx.x, b = blockIdx.y;
    const float* Ev = evecs + (size_t)b*VN*KN + (size_t)ch*128*KN;
    const float* Xp = g_x   + (size_t)b*VN*CN + (size_t)ch*128*CN;
    const float* mp = mass  + (size_t)b*VN    + (size_t)ch*128;
    ull acc[8][4]; acc_zero(acc);
    for (int v0 = 0; v0 < 128; v0 += 16) {
        load_B(As, Ev + (size_t)v0*KN, KN, tid);
        load_B_rowscale(Bs, Xp + (size_t)v0*CN, CN, mp + v0, tid);
        __syncthreads();
        mm_step16(As, Bs, acc, tx, ty);
        __syncthreads();
    }
    float* Cp = g_part + ((size_t)ch*BN + b)*KN*CN;
#pragma unroll
    for (int i = 0; i < 8; i++) { int r = row_of(i, ty);
#pragma unroll
        for (int p = 0; p < 4; p++) { int c0 = col_of(p, tx);
            float2 v = unpack2(acc[i][p]);
            *(float2*)(Cp + (size_t)r*CN + c0) = v;
        }
    }
}

// sT_h/l[b][c][k] = split( 8 * exp(-evals[b][k]*max(t[i][c],1e-8)) * sum_ch part[ch][b][k][c] )
__global__ void k_spec_reduce(const float* __restrict__ evals,
                              const float* __restrict__ t, int iblk)
{
    int b = blockIdx.y;
    int idx = blockIdx.x*256 + threadIdx.x;
    float sum = 0.f;
#pragma unroll 8
    for (int ch = 0; ch < NCHUNK; ch++)
        sum += g_part[((size_t)ch*BN + b)*KN*CN + idx];
    int k = idx >> 7, c = idx & 127;
    float ti = fmaxf(t[iblk*CN + c], 1e-8f);
    float s8 = 8.f * expf(-evals[b*KN + k]*ti) * sum;
    __half h = __float2half_rn(s8);
    size_t o = ((size_t)b*CN + c)*KN + k;
    g_sT_h[o] = h;
    g_sT_l[o] = __float2half_rn(s8 - __half2float(h));
}

// SIMT complex (verbatim from passing R6)
__global__ void __launch_bounds__(256) k_complex(const float* __restrict__ Are,
                                                 const float* __restrict__ Aim, int iblk)
{
    __shared__ __align__(16) float As[16*128], Bs[16*128];
    int tid = threadIdx.x, tx = tid & 15, ty = tid >> 4;
    int mt = blockIdx.x, b = blockIdx.y, z = blockIdx.z;
    size_t toff = (size_t)b*VN*CN + (size_t)mt*128*CN;
    const float* A1 = (z ? g_gy : g_gx) + toff;
    const float* A2 = (z ? g_gx : g_gy) + toff;
    const float* B1 = Are + (size_t)iblk*KN*CN;
    const float* B2 = Aim + (size_t)iblk*KN*CN;
    ull acc[8][4]; acc_zero(acc);
    gemm_acc(acc, A1, CN, B1, CN, 8, false,     As, Bs, tid, tx, ty);
    gemm_acc(acc, A2, CN, B2, CN, 8, (z == 0),  As, Bs, tid, tx, ty);
    float* Cp = (z ? g_bi : g_br) + toff;
#pragma unroll
    for (int i = 0; i < 8; i++) { int r = row_of(i, ty);
#pragma unroll
        for (int p = 0; p < 4; p++) { int c0 = col_of(p, tx);
            float2 v = unpack2(acc[i][p]);
            *(float2*)(Cp + (size_t)r*CN + c0) = v;
        }
    }
}

__global__ void k_tanh()
{
    size_t idx = (size_t)blockIdx.x*256 + threadIdx.x;
    g_gfeat[idx] = tanhf(fmaf(g_gx[idx], g_br[idx], g_gy[idx]*g_bi[idx]));
}

// SIMT mlp0/1/2 (verbatim from passing R6)
__global__ void __launch_bounds__(256) k_mlp0(const float* __restrict__ W0,
                                              const float* __restrict__ b0, int iblk)
{
    __shared__ __align__(16) float As[16*128], Bs[16*128];
    int tid = threadIdx.x, tx = tid & 15, ty = tid >> 4;
    int mt = blockIdx.x, b = blockIdx.y;
    size_t toff = (size_t)b*VN*CN + (size_t)mt*128*CN;
    const float* segs[3] = { g_x + toff, g_xdiff + toff, g_gfeat + toff };
    const float* W = W0 + (size_t)iblk*3*CN*CN;
    ull acc[8][4]; acc_zero(acc);
#pragma unroll
    for (int seg = 0; seg < 3; seg++)
        gemm_acc(acc, segs[seg], CN, W + (size_t)seg*CN*CN, CN, 8, false, As, Bs, tid, tx, ty);
    const float* bb = b0 + iblk*CN;
    float* Cp = g_h0 + toff;
#pragma unroll
    for (int i = 0; i < 8; i++) { int r = row_of(i, ty);
#pragma unroll
        for (int p = 0; p < 4; p++) { int c0 = col_of(p, tx);
            float2 v = unpack2(acc[i][p]);
            v.x = fmaxf(v.x + bb[c0],   0.f);
            v.y = fmaxf(v.y + bb[c0+1], 0.f);
            *(float2*)(Cp + (size_t)r*CN + c0) = v;
        }
    }
}

__global__ void __launch_bounds__(256) k_mlp1(const float* __restrict__ W1,
                                              const float* __restrict__ b1, int iblk)
{
    __shared__ __align__(16) float As[16*128], Bs[16*128];
    int tid = threadIdx.x, tx = tid & 15, ty = tid >> 4;
    int mt = blockIdx.x, b = blockIdx.y;
    size_t toff = (size_t)b*VN*CN + (size_t)mt*128*CN;
    ull acc[8][4]; acc_zero(acc);
    gemm_acc(acc, g_h0 + toff, CN, W1 + (size_t)iblk*CN*CN, CN, 8, false, As, Bs, tid, tx, ty);
    const float* bb = b1 + iblk*CN;
    float* Cp = g_h1 + toff;
#pragma unroll
    for (int i = 0; i < 8; i++) { int r = row_of(i, ty);
#pragma unroll
        for (int p = 0; p < 4; p++) { int c0 = col_of(p, tx);
            float2 v = unpack2(acc[i][p]);
            v.x = fmaxf(v.x + bb[c0],   0.f);
            v.y = fmaxf(v.y + bb[c0+1], 0.f);
            *(float2*)(Cp + (size_t)r*CN + c0) = v;
        }
    }
}

__global__ void __launch_bounds__(256) k_mlp2(const float* __restrict__ W2,
                                              const float* __restrict__ b2, int iblk)
{
    __shared__ __align__(16) float As[16*128], Bs[16*128];
    int tid = threadIdx.x, tx = tid & 15, ty = tid >> 4;
    int mt = blockIdx.x, b = blockIdx.y;
    size_t toff = (size_t)b*VN*CN + (size_t)mt*128*CN;
    ull acc[8][4]; acc_zero(acc);
    gemm_acc(acc, g_h1 + toff, CN, W2 + (size_t)iblk*CN*CN, CN, 8, false, As, Bs, tid, tx, ty);
    const float* bb = b2 + iblk*CN;
    float* Cp = g_x + toff;
#pragma unroll
    for (int i = 0; i < 8; i++) { int r = row_of(i, ty);
#pragma unroll
        for (int p = 0; p < 4; p++) { int c0 = col_of(p, tx);
            float2 v = unpack2(acc[i][p]);
            float2 xv = *(const float2*)(Cp + (size_t)r*CN + c0);
            v.x += xv.x + bb[c0];
            v.y += xv.y + bb[c0+1];
            *(float2*)(Cp + (size_t)r*CN + c0) = v;
        }
    }
}

__global__ void __launch_bounds__(256) k_out(const float* __restrict__ Wl,
                                             const float* __restrict__ bl,
                                             float* __restrict__ out)
{
    __shared__ __align__(16) float As[16*128], Bs[16*128];
    int tid = threadIdx.x, tx = tid & 15, ty = tid >> 4;
    int mt = blockIdx.x, b = blockIdx.y;
    size_t toff = (size_t)b*VN*CN + (size_t)mt*128*CN;
    ull acc[8][4]; acc_zero(acc);
    gemm_acc(acc, g_x + toff, CN, Wl, CN, 8, false, As, Bs, tid, tx, ty);
    float* Cp = out + toff;
#pragma unroll
    for (int i = 0; i < 8; i++) { int r = row_of(i, ty);
#pragma unroll
        for (int p = 0; p < 4; p++) { int c0 = col_of(p, tx);
            float2 v = unpack2(acc[i][p]);
            v.x += bl[c0]; v.y += bl[c0+1];
            *(float2*)(Cp + (size_t)r*CN + c0) = v;
        }
    }
}

// ---------------- launcher ----------------
extern "C" void kernel_launch(void* const* d_in, const int* in_sizes, int n_in,
                              void* d_out, int out_size)
{
    if (n_in < 19) return;
    const float* x_in  = (const float*)d_in[0];
    const float* mass  = (const float*)d_in[1];
    const float* evals = (const float*)d_in[2];
    const float* evecs = (const float*)d_in[3];
    const float* gradX = (const float*)d_in[4];
    const float* gradY = (const float*)d_in[5];
    const float* Wf    = (const float*)d_in[6];
    const float* bf    = (const float*)d_in[7];
    const float* Wl    = (const float*)d_in[8];
    const float* bl    = (const float*)d_in[9];
    const float* t     = (const float*)d_in[10];
    const float* Are   = (const float*)d_in[11];
    const float* Aim   = (const float*)d_in[12];
    const float* W0    = (const float*)d_in[13];
    const float* b0    = (const float*)d_in[14];
    const float* W1    = (const float*)d_in[15];
    const float* b1    = (const float*)d_in[16];
    const float* W2    = (const float*)d_in[17];
    const float* b2    = (const float*)d_in[18];

    // Only grad_pre needs >48KB dynamic smem (pre-loop; validated in R6).
    cudaFuncSetAttribute(k_grad_pre_mma, cudaFuncAttributeMaxDynamicSharedMemorySize, SMEM_MMA);

    // one-time preps
    k_evT<<<dim3(KN/32, VN/32, BN), dim3(32, 8)>>>(evecs);
    k_lin_in<<<BN*VN/128, 256>>>(x_in, Wf, bf);
    k_grad_pre_mma<<<dim3(VN/128, BN, 2), 256, SMEM_MMA>>>(gradX, gradY);

    for (int i = 0; i < NBLK; i++) {
        k_spec_part  <<<dim3(NCHUNK, BN), 256>>>(evecs, mass);
        k_spec_reduce<<<dim3(KN*CN/256, BN), 256>>>(evals, t, i);
        k_fb3_mma    <<<dim3(VN/128, BN, 3), 256>>>(evecs);   // static smem, no attribute
        k_complex    <<<dim3(VN/128, BN, 2), 256>>>(Are, Aim, i);
        k_tanh       <<<BN*VN*CN/256, 256>>>();
        k_mlp0       <<<dim3(VN/128, BN), 256>>>(W0, b0, i);
        k_mlp1       <<<dim3(VN/128, BN), 256>>>(W1, b1, i);
        k_mlp2       <<<dim3(VN/128, BN), 256>>>(W2, b2, i);
    }
    k_out<<<dim3(VN/128, BN), 256>>>(Wl, bl, (float*)d_out);
}